// round 7
// baseline (speedup 1.0000x reference)
#include <cuda_runtime.h>

#define B_  2048
#define E_  32
#define N_  32
#define D_  64
#define BE_ (B_*E_)

// One warp processes TWO independent (b,e) pairs interleaved in the same
// instruction stream: while pair A sits in its shfl reduce/softmax latency
// chain, pair B's loads are in flight (and vice versa). Lane l covers dims
// [4q..4q+3], q = l&15; each LDG.128 fetches two neighbor rows.
// Warps own contiguous pair ranges (26-27 pairs): 0.2% imbalance + better
// DRAM row locality.
__global__ __launch_bounds__(256, 2)
void sum_aggregator_kernel(const float* __restrict__ selfv,   // [B,E,D]
                           const float* __restrict__ nbv,     // [B,E,N,D]
                           const float* __restrict__ relv,    // [B,E,N,D]
                           const float* __restrict__ userv,   // [B,D]
                           const float* __restrict__ W,       // [D,D] row-major
                           const float* __restrict__ bl,      // [D]
                           float* __restrict__ out,           // [B,E,D]
                           int total_warps)
{
    __shared__ float4 Wa[16][32];   // Wa[c][l] = W[2l][4c..4c+3]
    __shared__ float4 Wb[16][32];   // Wb[c][l] = W[2l+1][4c..4c+3]

    const int tid  = threadIdx.x;
    const int lane = tid & 31;
    const int wid  = tid >> 5;
    const int q    = lane & 15;

    for (int i = tid; i < 16 * 32; i += 256) {
        int c = i >> 5, l = i & 31;
        Wa[c][l] = *reinterpret_cast<const float4*>(W + (2*l  )*D_ + 4*c);
        Wb[c][l] = *reinterpret_cast<const float4*>(W + (2*l+1)*D_ + 4*c);
    }
    __syncthreads();

    const float2 bb = *reinterpret_cast<const float2*>(bl + 2*lane);

    // Contiguous partition: warp gw owns [start, start+cnt)
    const int gw   = blockIdx.x * 8 + wid;
    const int bas  = BE_ / total_warps;
    const int rem  = BE_ % total_warps;
    const int cnt  = bas + (gw < rem ? 1 : 0);
    const int start = gw * bas + (gw < rem ? gw : rem);
    const int end  = start + cnt;

    int p = start;
    // ================= dual-pair main loop =================
    for (; p + 1 < end; p += 2) {
        const int pA = p, pB = p + 1;
        const float4 uA = *reinterpret_cast<const float4*>(userv + (size_t)(pA >> 5)*D_ + 4*q);
        const float4 uB = *reinterpret_cast<const float4*>(userv + (size_t)(pB >> 5)*D_ + 4*q);
        const float* relpA = relv + (size_t)pA * (N_*D_);
        const float* relpB = relpA + (N_*D_);
        const float* nbpA  = nbv  + (size_t)pA * (N_*D_);
        const float* nbpB  = nbpA + (N_*D_);

        // ---- Pass 1: both rel tiles, sync-free (32 LDG.128 batchable) ----
        float vA[16], vB[16];
        #pragma unroll
        for (int i = 0; i < 16; i++) {
            float4 rA = *reinterpret_cast<const float4*>(relpA + i*128 + 4*lane);
            float4 rB = *reinterpret_cast<const float4*>(relpB + i*128 + 4*lane);
            vA[i] = uA.x*rA.x + uA.y*rA.y + uA.z*rA.z + uA.w*rA.w;
            vB[i] = uB.x*rB.x + uB.y*rB.y + uB.z*rB.z + uB.w*rB.w;
        }

        // ---- Reduce-scatter (two independent shfl streams interleave) ----
        #pragma unroll
        for (int off = 8; off >= 1; off >>= 1) {
            const bool up = (lane & off) != 0;
            #pragma unroll
            for (int k = 0; k < off; k++) {
                float mA = up ? vA[off + k] : vA[k];
                float oA = up ? vA[k]       : vA[off + k];
                float mB = up ? vB[off + k] : vB[k];
                float oB = up ? vB[k]       : vB[off + k];
                vA[k] = mA + __shfl_xor_sync(0xffffffffu, oA, off);
                vB[k] = mB + __shfl_xor_sync(0xffffffffu, oB, off);
            }
        }
        float eA = __expf(vA[0] * (1.0f / (float)D_));
        float eB = __expf(vB[0] * (1.0f / (float)D_));
        float sumA = eA, sumB = eB;
        #pragma unroll
        for (int off = 16; off >= 1; off >>= 1) {
            sumA += __shfl_xor_sync(0xffffffffu, sumA, off);
            sumB += __shfl_xor_sync(0xffffffffu, sumB, off);
        }
        const float aA = eA / (sumA * (float)N_);
        const float aB = eB / (sumB * (float)N_);

        // ---- Pass 2: both nb tiles ----
        float4 accA = make_float4(0.f,0.f,0.f,0.f);
        float4 accB = make_float4(0.f,0.f,0.f,0.f);
        #pragma unroll
        for (int i = 0; i < 16; i++) {
            float4 xA = *reinterpret_cast<const float4*>(nbpA + i*128 + 4*lane);
            float4 xB = *reinterpret_cast<const float4*>(nbpB + i*128 + 4*lane);
            float anA = __shfl_sync(0xffffffffu, aA, i + (lane & 16));
            float anB = __shfl_sync(0xffffffffu, aB, i + (lane & 16));
            accA.x = fmaf(anA, xA.x, accA.x);  accA.y = fmaf(anA, xA.y, accA.y);
            accA.z = fmaf(anA, xA.z, accA.z);  accA.w = fmaf(anA, xA.w, accA.w);
            accB.x = fmaf(anB, xB.x, accB.x);  accB.y = fmaf(anB, xB.y, accB.y);
            accB.z = fmaf(anB, xB.z, accB.z);  accB.w = fmaf(anB, xB.w, accB.w);
        }
        accA.x += __shfl_xor_sync(0xffffffffu, accA.x, 16);
        accA.y += __shfl_xor_sync(0xffffffffu, accA.y, 16);
        accA.z += __shfl_xor_sync(0xffffffffu, accA.z, 16);
        accA.w += __shfl_xor_sync(0xffffffffu, accA.w, 16);
        accB.x += __shfl_xor_sync(0xffffffffu, accB.x, 16);
        accB.y += __shfl_xor_sync(0xffffffffu, accB.y, 16);
        accB.z += __shfl_xor_sync(0xffffffffu, accB.z, 16);
        accB.w += __shfl_xor_sync(0xffffffffu, accB.w, 16);

        const float4 svA = *reinterpret_cast<const float4*>(selfv + (size_t)pA*D_ + 4*q);
        const float4 svB = *reinterpret_cast<const float4*>(selfv + (size_t)pB*D_ + 4*q);
        float4 oA = make_float4(svA.x+accA.x, svA.y+accA.y, svA.z+accA.z, svA.w+accA.w);
        float4 oB = make_float4(svB.x+accB.x, svB.y+accB.y, svB.z+accB.z, svB.w+accB.w);

        // ---- Linear for both (LDS of W shared between the two streams) ----
        float y0A = bb.x, y1A = bb.y, y0B = bb.x, y1B = bb.y;
        #pragma unroll
        for (int c = 0; c < 16; c++) {
            float4 wa = Wa[c][lane];
            float4 wb = Wb[c][lane];
            float oxA = __shfl_sync(0xffffffffu, oA.x, c);
            float oyA = __shfl_sync(0xffffffffu, oA.y, c);
            float ozA = __shfl_sync(0xffffffffu, oA.z, c);
            float owA = __shfl_sync(0xffffffffu, oA.w, c);
            float oxB = __shfl_sync(0xffffffffu, oB.x, c);
            float oyB = __shfl_sync(0xffffffffu, oB.y, c);
            float ozB = __shfl_sync(0xffffffffu, oB.z, c);
            float owB = __shfl_sync(0xffffffffu, oB.w, c);
            y0A = fmaf(oxA, wa.x, fmaf(oyA, wa.y, fmaf(ozA, wa.z, fmaf(owA, wa.w, y0A))));
            y1A = fmaf(oxA, wb.x, fmaf(oyA, wb.y, fmaf(ozA, wb.z, fmaf(owA, wb.w, y1A))));
            y0B = fmaf(oxB, wa.x, fmaf(oyB, wa.y, fmaf(ozB, wa.z, fmaf(owB, wa.w, y0B))));
            y1B = fmaf(oxB, wb.x, fmaf(oyB, wb.y, fmaf(ozB, wb.z, fmaf(owB, wb.w, y1B))));
        }
        *reinterpret_cast<float2*>(out + (size_t)pA*D_ + 2*lane) =
            make_float2(fmaxf(y0A, 0.f), fmaxf(y1A, 0.f));
        *reinterpret_cast<float2*>(out + (size_t)pB*D_ + 2*lane) =
            make_float2(fmaxf(y0B, 0.f), fmaxf(y1B, 0.f));
    }

    // ================= single-pair tail =================
    if (p < end) {
        const float4 u = *reinterpret_cast<const float4*>(userv + (size_t)(p >> 5)*D_ + 4*q);
        const float* relp = relv + (size_t)p * (N_*D_);
        const float* nbp  = nbv  + (size_t)p * (N_*D_);

        float v[16];
        #pragma unroll
        for (int i = 0; i < 16; i++) {
            float4 r = *reinterpret_cast<const float4*>(relp + i*128 + 4*lane);
            v[i] = u.x*r.x + u.y*r.y + u.z*r.z + u.w*r.w;
        }
        #pragma unroll
        for (int off = 8; off >= 1; off >>= 1) {
            const bool up = (lane & off) != 0;
            #pragma unroll
            for (int k = 0; k < off; k++) {
                float mine = up ? v[off + k] : v[k];
                float oth  = up ? v[k]       : v[off + k];
                v[k] = mine + __shfl_xor_sync(0xffffffffu, oth, off);
            }
        }
        float e = __expf(v[0] * (1.0f / (float)D_));
        float sum = e;
        #pragma unroll
        for (int off = 16; off >= 1; off >>= 1)
            sum += __shfl_xor_sync(0xffffffffu, sum, off);
        const float a = e / (sum * (float)N_);

        float4 acc = make_float4(0.f,0.f,0.f,0.f);
        #pragma unroll
        for (int i = 0; i < 16; i++) {
            float4 x = *reinterpret_cast<const float4*>(nbp + i*128 + 4*lane);
            float an = __shfl_sync(0xffffffffu, a, i + (lane & 16));
            acc.x = fmaf(an, x.x, acc.x);
            acc.y = fmaf(an, x.y, acc.y);
            acc.z = fmaf(an, x.z, acc.z);
            acc.w = fmaf(an, x.w, acc.w);
        }
        acc.x += __shfl_xor_sync(0xffffffffu, acc.x, 16);
        acc.y += __shfl_xor_sync(0xffffffffu, acc.y, 16);
        acc.z += __shfl_xor_sync(0xffffffffu, acc.z, 16);
        acc.w += __shfl_xor_sync(0xffffffffu, acc.w, 16);

        const float4 sv = *reinterpret_cast<const float4*>(selfv + (size_t)p*D_ + 4*q);
        float4 o = make_float4(sv.x+acc.x, sv.y+acc.y, sv.z+acc.z, sv.w+acc.w);

        float y0 = bb.x, y1 = bb.y;
        #pragma unroll
        for (int c = 0; c < 16; c++) {
            float ox = __shfl_sync(0xffffffffu, o.x, c);
            float oy = __shfl_sync(0xffffffffu, o.y, c);
            float oz = __shfl_sync(0xffffffffu, o.z, c);
            float ow = __shfl_sync(0xffffffffu, o.w, c);
            float4 wa = Wa[c][lane];
            float4 wb = Wb[c][lane];
            y0 = fmaf(ox, wa.x, fmaf(oy, wa.y, fmaf(oz, wa.z, fmaf(ow, wa.w, y0))));
            y1 = fmaf(ox, wb.x, fmaf(oy, wb.y, fmaf(oz, wb.z, fmaf(ow, wb.w, y1))));
        }
        *reinterpret_cast<float2*>(out + (size_t)p*D_ + 2*lane) =
            make_float2(fmaxf(y0, 0.f), fmaxf(y1, 0.f));
    }
}

extern "C" void kernel_launch(void* const* d_in, const int* in_sizes, int n_in,
                              void* d_out, int out_size)
{
    const float* selfv = (const float*)d_in[0];  // self_vectors      [B,E,D]
    const float* nbv   = (const float*)d_in[1];  // neighbor_vectors  [B,E,N,D]
    const float* relv  = (const float*)d_in[2];  // neighbor_relations[B,E,N,D]
    const float* userv = (const float*)d_in[3];  // user_embeddings   [B,D]
    // d_in[4] = masks (unused)
    const float* W     = (const float*)d_in[5];  // [D,D]
    const float* bl    = (const float*)d_in[6];  // [D]
    float* out = (float*)d_out;

    int dev = 0, sms = 152, occ = 0;
    cudaGetDevice(&dev);
    cudaDeviceGetAttribute(&sms, cudaDevAttrMultiProcessorCount, dev);
    cudaOccupancyMaxActiveBlocksPerMultiprocessor(&occ, sum_aggregator_kernel, 256, 0);
    if (occ < 1) occ = 1;
    if (occ > 2) occ = 2;    // 16 warps/SM x 2 pairs = 32 streams/SM
    int blocks = occ * sms;
    int max_blocks = BE_ / 8;
    if (blocks > max_blocks) blocks = max_blocks;
    int total_warps = blocks * 8;

    sum_aggregator_kernel<<<blocks, 256>>>(selfv, nbv, relv, userv, W, bl, out,
                                           total_warps);
}